// round 6
// baseline (speedup 1.0000x reference)
#include <cuda_runtime.h>
#include <cuda_bf16.h>
#include <cstdint>

// Problem constants (fixed shapes)
#define EDGES   100000
#define NSRC    10000
#define NDST    10000
#define CCH     128     // channels
#define K1      64      // MLP_IN
#define HID     128     // MLP_HID
#define WN      512     // W_NUMEL = 4*128
#define OUTC    2048    // C * SH_DIM

// Scratch (device globals: no allocation allowed)
__device__ __nv_bfloat16 g_Hh[(size_t)EDGES * HID];   // 25.6 MB  H hi (bf16 split)
__device__ __nv_bfloat16 g_Hl[(size_t)EDGES * HID];   // 25.6 MB  H lo
__device__ float         g_W1T[HID * K1];             // W1^T * (1/sqrt(64))
__device__ __nv_bfloat16 g_W2Th[WN * HID];            // W2^T hi, prescaled
__device__ __nv_bfloat16 g_W2Tl[WN * HID];            // W2^T lo

// ---------------------------------------------------------------------------
// PTX helpers (family-compatible only: FFMA2, ldmatrix, mma.sync)
// ---------------------------------------------------------------------------
__device__ __forceinline__ void ffma2(unsigned long long& d,
                                      unsigned long long a,
                                      unsigned long long b) {
    asm("fma.rn.f32x2 %0, %1, %2, %0;" : "+l"(d) : "l"(a), "l"(b));
}

__device__ __forceinline__ uint32_t smem_u32(const void* p) {
    uint32_t a;
    asm("{ .reg .u64 t; cvta.to.shared.u64 t, %1; cvt.u32.u64 %0, t; }"
        : "=r"(a) : "l"(p));
    return a;
}

__device__ __forceinline__ void ldsm4(uint32_t* r, uint32_t addr) {
    asm volatile("ldmatrix.sync.aligned.m8n8.x4.shared.b16 {%0,%1,%2,%3}, [%4];"
                 : "=r"(r[0]), "=r"(r[1]), "=r"(r[2]), "=r"(r[3]) : "r"(addr));
}

__device__ __forceinline__ void mma_bf16(float* c, const uint32_t* a,
                                         const uint32_t* b) {
    asm volatile(
        "mma.sync.aligned.m16n8k16.row.col.f32.bf16.bf16.f32 "
        "{%0,%1,%2,%3}, {%4,%5,%6,%7}, {%8,%9}, {%0,%1,%2,%3};"
        : "+f"(c[0]), "+f"(c[1]), "+f"(c[2]), "+f"(c[3])
        : "r"(a[0]), "r"(a[1]), "r"(a[2]), "r"(a[3]), "r"(b[0]), "r"(b[1]));
}

// ---------------------------------------------------------------------------
// Prep: transpose + prescale weights.
// ---------------------------------------------------------------------------
__global__ void prep_w_kernel(const float* __restrict__ W1,
                              const float* __restrict__ W2) {
    int i = blockIdx.x * blockDim.x + threadIdx.x;
    if (i < K1 * HID) {
        int k = i / HID, n = i % HID;
        g_W1T[n * K1 + k] = W1[i] * 0.125f;               // 1/sqrt(64)
    }
    int j = i - K1 * HID;
    if (j >= 0 && j < HID * WN) {
        int k = j / WN, n = j % WN;
        float v = W2[j] * 0.08838834764831843f;           // 1/sqrt(128)
        __nv_bfloat16 h = __float2bfloat16_rn(v);
        g_W2Th[n * HID + k] = h;
        g_W2Tl[n * HID + k] = __float2bfloat16_rn(v - __bfloat162float(h));
    }
}

// ---------------------------------------------------------------------------
// GEMM1 (fp32 FFMA2): H = silu(edge_emb @ W1s), emitted as bf16 hi/lo split.
// ---------------------------------------------------------------------------
__global__ void __launch_bounds__(256, 1)
gemm1_kernel(const float* __restrict__ A, const float* __restrict__ BT,
             __nv_bfloat16* __restrict__ OH, __nv_bfloat16* __restrict__ OL) {
    __shared__ float As[128][34];
    __shared__ float Bs[128][34];

    const int m0 = blockIdx.x * 128;
    const int tid = threadIdx.x;
    const int tx = tid & 15;
    const int ty = tid >> 4;

    unsigned long long acc[8][8];
#pragma unroll
    for (int i = 0; i < 8; i++)
#pragma unroll
        for (int j = 0; j < 8; j++) acc[i][j] = 0ULL;

    for (int kk = 0; kk < 64; kk += 32) {
#pragma unroll
        for (int i = tid; i < 1024; i += 256) {
            int r = i >> 3, c4 = i & 7;
            int gm = m0 + r;
            float4 v = make_float4(0.f, 0.f, 0.f, 0.f);
            if (gm < EDGES)
                v = *(const float4*)(A + (size_t)gm * 64 + kk + c4 * 4);
            *(float2*)&As[r][c4 * 4]     = make_float2(v.x, v.y);
            *(float2*)&As[r][c4 * 4 + 2] = make_float2(v.z, v.w);
        }
#pragma unroll
        for (int i = tid; i < 1024; i += 256) {
            int r = i >> 3, c4 = i & 7;
            float4 v = *(const float4*)(BT + (size_t)r * 64 + kk + c4 * 4);
            *(float2*)&Bs[r][c4 * 4]     = make_float2(v.x, v.y);
            *(float2*)&Bs[r][c4 * 4 + 2] = make_float2(v.z, v.w);
        }
        __syncthreads();

#pragma unroll
        for (int k2 = 0; k2 < 16; k2++) {
            unsigned long long ap[8], bp[8];
#pragma unroll
            for (int i = 0; i < 8; i++)
                ap[i] = *(const unsigned long long*)&As[ty + 16 * i][2 * k2];
#pragma unroll
            for (int j = 0; j < 8; j++)
                bp[j] = *(const unsigned long long*)&Bs[tx + 16 * j][2 * k2];
#pragma unroll
            for (int i = 0; i < 8; i++)
#pragma unroll
                for (int j = 0; j < 8; j++) ffma2(acc[i][j], ap[i], bp[j]);
        }
        __syncthreads();
    }

#pragma unroll
    for (int i = 0; i < 8; i++) {
        int gm = m0 + ty + 16 * i;
        if (gm < EDGES) {
#pragma unroll
            for (int j = 0; j < 8; j++) {
                unsigned int lo = (unsigned int)acc[i][j];
                unsigned int hi = (unsigned int)(acc[i][j] >> 32);
                float v = __uint_as_float(lo) + __uint_as_float(hi);
                v = v / (1.0f + __expf(-v));                 // silu
                __nv_bfloat16 h = __float2bfloat16_rn(v);
                size_t o = (size_t)gm * 128 + tx + 16 * j;
                OH[o] = h;
                OL[o] = __float2bfloat16_rn(v - __bfloat162float(h));
            }
        }
    }
}

// ---------------------------------------------------------------------------
// FUSED GEMM2 + tensor product + scatter.
// CTA = 128 edges. For each l-chunk (N=128 == one l block of W_NUMEL):
//   mma.sync 3-pass split-precision -> acc regs -> stage (smem fp32)
//   -> warp-per-edge coalesced atomic scatter into out.
// TPW never touches global memory.
// ---------------------------------------------------------------------------
#define FTILE     34816                    // 128 rows * 272B (pad-136 bf16)
#define FSM_AH    0
#define FSM_AL    (FTILE)
#define FSM_BH    (2 * FTILE)
#define FSM_BL    (3 * FTILE)
#define FSM_STAGE (4 * FTILE)              // 139264
#define FST_STR   132                      // stage row stride in floats
#define FSM_SH    (FSM_STAGE + 128 * FST_STR * 4)   // 206848
#define FSM_DST   (FSM_SH + 128 * 16 * 4)           // 215040
#define FSM_SRC   (FSM_DST + 512)                   // 215552
#define FSM_TOTAL (FSM_SRC + 512)                   // 216064

template <int D, int NIT, int MAGIC, int OBASE, int SHOFF>
__device__ __forceinline__ void scatter_chunk(
    int m0, int wid, int lane, const float* __restrict__ stage,
    const float* __restrict__ s_sh, const int* __restrict__ s_src,
    const int* __restrict__ s_dst, const float* __restrict__ X,
    float* __restrict__ out) {
#pragma unroll 1
    for (int i = 0; i < 16; i++) {
        int le = wid + 8 * i;
        int e = m0 + le;
        if (e >= EDGES) continue;
        const float* xs = X + (size_t)s_src[le] * 128;
        float* orow = out + (size_t)s_dst[le] * OUTC + OBASE;
        const float* tw = stage + le * FST_STR;
        const float* shp = s_sh + le * 16 + SHOFF;
#pragma unroll
        for (int it = 0; it < NIT; it++) {
            int pp = it * 32 + lane;
            int c, m;
            if (D == 1) { c = pp; m = 0; }
            else        { c = (pp * MAGIC) >> 16; m = pp - c * D; }
            atomicAdd(orow + pp, tw[c] * xs[c] * shp[m]);
        }
    }
}

__global__ void __launch_bounds__(256, 1)
fused_g2_tp_kernel(const __nv_bfloat16* __restrict__ Ah,
                   const __nv_bfloat16* __restrict__ Al,
                   const __nv_bfloat16* __restrict__ Bh,
                   const __nv_bfloat16* __restrict__ Bl,
                   const float* __restrict__ X,
                   const float* __restrict__ SH,
                   const int* __restrict__ src,
                   const int* __restrict__ dst,
                   float* __restrict__ out) {
    extern __shared__ char smem[];
    const uint32_t sbase = smem_u32(smem);
    const int tid  = threadIdx.x;
    const int wid  = tid >> 5;
    const int lane = tid & 31;
    const int m0   = blockIdx.x * 128;

    float* stage = (float*)(smem + FSM_STAGE);
    float* s_sh  = (float*)(smem + FSM_SH);
    int*   s_dst = (int*)(smem + FSM_DST);
    int*   s_src = (int*)(smem + FSM_SRC);

    // ---- Stage A hi/lo (zero-padded), edge metadata, sh rows
    for (int q = tid; q < 2048; q += 256) {
        int r = q >> 4, c = q & 15;
        uint32_t so = (uint32_t)r * 272 + (uint32_t)c * 16;
        int gm = m0 + r;
        uint4 vh = make_uint4(0, 0, 0, 0), vl = vh;
        if (gm < EDGES) {
            vh = *(const uint4*)(Ah + (size_t)gm * 128 + c * 8);
            vl = *(const uint4*)(Al + (size_t)gm * 128 + c * 8);
        }
        *(uint4*)(smem + FSM_AH + so) = vh;
        *(uint4*)(smem + FSM_AL + so) = vl;
    }
    if (tid < 128) {
        int e = m0 + tid;
        s_dst[tid] = (e < EDGES) ? dst[e] : 0;
        s_src[tid] = (e < EDGES) ? src[e] : 0;
    }
    for (int q = tid; q < 512; q += 256) {          // 128 edges * 4 float4
        int e = q >> 2, j = q & 3;
        float4 v = make_float4(0.f, 0.f, 0.f, 0.f);
        if (m0 + e < EDGES)
            v = *(const float4*)(SH + (size_t)(m0 + e) * 16 + j * 4);
        *(float4*)(s_sh + e * 16 + j * 4) = v;
    }

    // ldmatrix address components (identical layout to the r5 GEMM2)
    const int wm = wid & 3;           // M offset wm*32
    const int wn = wid >> 2;          // N offset wn*64
    const uint32_t a_row = (uint32_t)(wm * 32 + (lane & 15));
    const uint32_t a_kof = (uint32_t)((lane >> 4) * 16);
    const uint32_t b_row = (uint32_t)(wn * 64 + (lane & 7) + (lane >> 4) * 8);
    const uint32_t b_kof = (uint32_t)(((lane >> 3) & 1) * 16);

    const int er = wm * 32 + (lane >> 2);
    const int ec = wn * 64 + 2 * (lane & 3);

#pragma unroll 1
    for (int l = 0; l < 4; l++) {
        // ---- Load B l-chunk (hi/lo) from L2-hot W2T
        for (int q = tid; q < 2048; q += 256) {
            int r = q >> 4, c = q & 15;
            uint32_t so = (uint32_t)r * 272 + (uint32_t)c * 16;
            size_t gb = (size_t)(l * 128 + r) * 128 + c * 8;
            *(uint4*)(smem + FSM_BH + so) = *(const uint4*)(Bh + gb);
            *(uint4*)(smem + FSM_BL + so) = *(const uint4*)(Bl + gb);
        }
        __syncthreads();   // B ready; also: all warps done with prior scatter

        float acc[2][8][4];
#pragma unroll
        for (int i = 0; i < 2; i++)
#pragma unroll
            for (int j = 0; j < 8; j++)
#pragma unroll
                for (int v = 0; v < 4; v++) acc[i][j][v] = 0.f;

        // ---- Split-precision passes: (Ah,Bh), (Ah,Bl), (Al,Bh)
#pragma unroll
        for (int p = 0; p < 3; p++) {
            const uint32_t abase = sbase + ((p == 2) ? FSM_AL : FSM_AH);
            const uint32_t bbase = sbase + ((p == 1) ? FSM_BL : FSM_BH);
            const uint32_t aaddr0 = abase + a_row * 272 + a_kof;
            const uint32_t baddr0 = bbase + b_row * 272 + b_kof;
#pragma unroll
            for (int ks = 0; ks < 8; ks++) {
                uint32_t afr[2][4], bfr[4][4];
#pragma unroll
                for (int mt = 0; mt < 2; mt++)
                    ldsm4(afr[mt], aaddr0 + (uint32_t)(mt * 16) * 272 + ks * 32);
#pragma unroll
                for (int np = 0; np < 4; np++)
                    ldsm4(bfr[np], baddr0 + (uint32_t)(np * 16) * 272 + ks * 32);
#pragma unroll
                for (int mt = 0; mt < 2; mt++)
#pragma unroll
                    for (int nt = 0; nt < 8; nt++)
                        mma_bf16(acc[mt][nt], afr[mt], &bfr[nt >> 1][(nt & 1) * 2]);
            }
        }

        // ---- Stage acc chunk into smem (fp32, pad-132 stride)
#pragma unroll
        for (int mt = 0; mt < 2; mt++) {
            int r0 = er + mt * 16;
#pragma unroll
            for (int nt = 0; nt < 8; nt++) {
                int c = ec + nt * 8;
                *(float2*)(stage + (size_t)r0 * FST_STR + c) =
                    make_float2(acc[mt][nt][0], acc[mt][nt][1]);
                *(float2*)(stage + (size_t)(r0 + 8) * FST_STR + c) =
                    make_float2(acc[mt][nt][2], acc[mt][nt][3]);
            }
        }
        __syncthreads();

        // ---- Tensor product + coalesced atomic scatter for this l
        if (l == 0)
            scatter_chunk<1, 4, 0, 0, 0>(m0, wid, lane, stage, s_sh, s_src,
                                         s_dst, X, out);
        else if (l == 1)
            scatter_chunk<3, 12, 21846, 128, 1>(m0, wid, lane, stage, s_sh,
                                                s_src, s_dst, X, out);
        else if (l == 2)
            scatter_chunk<5, 20, 13108, 512, 4>(m0, wid, lane, stage, s_sh,
                                                s_src, s_dst, X, out);
        else
            scatter_chunk<7, 28, 9363, 1152, 9>(m0, wid, lane, stage, s_sh,
                                                s_src, s_dst, X, out);
    }
}

// ---------------------------------------------------------------------------
// Launch
// ---------------------------------------------------------------------------
extern "C" void kernel_launch(void* const* d_in, const int* in_sizes, int n_in,
                              void* d_out, int out_size) {
    const float* src_features = (const float*)d_in[0];
    const float* edge_sh      = (const float*)d_in[1];
    const float* edge_emb     = (const float*)d_in[2];
    const float* W1           = (const float*)d_in[3];
    const float* W2           = (const float*)d_in[4];
    const int*   src          = (const int*)d_in[5];
    const int*   dst          = (const int*)d_in[6];
    float*       out          = (float*)d_out;

    __nv_bfloat16 *pHh, *pHl, *pW2Th, *pW2Tl;
    float *pW1T;
    cudaGetSymbolAddress((void**)&pHh,   g_Hh);
    cudaGetSymbolAddress((void**)&pHl,   g_Hl);
    cudaGetSymbolAddress((void**)&pW1T,  g_W1T);
    cudaGetSymbolAddress((void**)&pW2Th, g_W2Th);
    cudaGetSymbolAddress((void**)&pW2Tl, g_W2Tl);

    cudaFuncSetAttribute(fused_g2_tp_kernel,
                         cudaFuncAttributeMaxDynamicSharedMemorySize, FSM_TOTAL);

    // Zero output (atomics accumulate into it)
    cudaMemsetAsync(out, 0, (size_t)NDST * OUTC * sizeof(float));

    // Transpose + prescale weights (W2 -> bf16 hi/lo split)
    prep_w_kernel<<<(K1 * HID + HID * WN + 255) / 256, 256>>>(W1, W2);

    // GEMM1 + silu -> bf16 split H
    gemm1_kernel<<<(EDGES + 127) / 128, 256>>>(edge_emb, pW1T, pHh, pHl);

    // Fused GEMM2 (mma.sync split-precision) + tensor product + scatter
    fused_g2_tp_kernel<<<(EDGES + 127) / 128, 256, FSM_TOTAL>>>(
        pHh, pHl, pW2Th, pW2Tl, src_features, edge_sh, src, dst, out);
}